// round 12
// baseline (speedup 1.0000x reference)
#include <cuda_runtime.h>
#include <cuda_fp16.h>

#define NQ 20
typedef unsigned long long u64;
typedef unsigned int u32;

// 64MB scratch: fp16x2 intermediate for all 16 batches
__device__ u32 g_scratch[16u << 20];

// ---------------- f32x2 helpers (packed 2xfp32 ops, sm_103a) ----------------
__device__ __forceinline__ u64 pk(float lo, float hi) {
    u64 r; asm("mov.b64 %0,{%1,%2};" : "=l"(r) : "f"(lo), "f"(hi)); return r;
}
__device__ __forceinline__ void upk(u64 p, float& lo, float& hi) {
    asm("mov.b64 {%0,%1},%2;" : "=f"(lo), "=f"(hi) : "l"(p));
}
__device__ __forceinline__ u64 f2mul(u64 a, u64 b) {
    u64 r; asm("mul.rn.f32x2 %0,%1,%2;" : "=l"(r) : "l"(a), "l"(b)); return r;
}
__device__ __forceinline__ u64 f2fma(u64 a, u64 b, u64 c) {
    u64 r; asm("fma.rn.f32x2 %0,%1,%2,%3;" : "=l"(r) : "l"(a), "l"(b), "l"(c)); return r;
}

// ---------------- fast-Givens RX stages ----------------
// Unscaled update with t = tan(th/2):
//   ax' = ax + t*by ; ay' = ay - t*bx ; bx' = bx + t*ay ; by' = by - t*ax
// True result = (prod of cos) * unscaled; scale applied once at the end.

template<int NP>
__device__ __forceinline__ void fg_stage0(u64* PX, u64* PY, float tt)
{
#pragma unroll
    for (int q = 0; q < NP; ++q) {
        float xl, xh, yl, yh;
        upk(PX[q], xl, xh); upk(PY[q], yl, yh);
        PX[q] = pk(fmaf(tt, yh, xl), fmaf(tt, yl, xh));
        PY[q] = pk(fmaf(-tt, xh, yl), fmaf(-tt, xl, yh));
    }
}

template<int NP>
__device__ __forceinline__ void fg_mask(u64* PX, u64* PY, float tv, int pm)
{
    u64 t2  = pk(tv,  tv);
    u64 tn2 = pk(-tv, -tv);
#pragma unroll
    for (int q = 0; q < NP; ++q) {
        if (!(q & pm)) {
            const int q2 = q | pm;
            u64 ax = PX[q], bx = PX[q2];
            PX[q]  = f2fma(t2,  PY[q2], ax);
            PX[q2] = f2fma(t2,  PY[q],  bx);
            PY[q]  = f2fma(tn2, bx, PY[q]);
            PY[q2] = f2fma(tn2, ax, PY[q2]);
        }
    }
}

template<int NP, int JMAX>
__device__ __forceinline__ void fg_tail(u64* PX, u64* PY, const float* t)
{
#pragma unroll
    for (int j = 1; j <= JMAX; ++j)
        fg_mask<NP>(PX, PY, t[j], 1 << (j - 1));
}

template<int NP>
__device__ __forceinline__ void fg_scale(u64* PX, u64* PY, float C)
{
    u64 C2 = pk(C, C);
#pragma unroll
    for (int q = 0; q < NP; ++q) {
        PX[q] = f2mul(C2, PX[q]);
        PY[q] = f2mul(C2, PY[q]);
    }
}

// qubit i = most-significant bit => global bit g maps to theta index (19-g)
template<int N>
__device__ __forceinline__ float load_tc(const float* __restrict__ thetas, int b,
                                         int gbase, float* t)
{
    float C = 1.0f;
#pragma unroll
    for (int j = 0; j < N; ++j) {
        float th = thetas[b * NQ + (NQ - 1 - (gbase + j))];
        float s, c;
        __sincosf(0.5f * th, &s, &c);
        t[j] = __fdividef(s, c);
        C *= c;
    }
    return C;
}

// ---------------------------------------------------------------------------
// Pass A (unchanged, R7-best): global bits 0..9, all 16 batches. Warp owns
// 1024 contiguous elements. phi streamed in (__ldcs); fp16x2 to scratch.
// ---------------------------------------------------------------------------
__global__ void __launch_bounds__(256)
rx_a(const float* __restrict__ phi, const float* __restrict__ thetas)
{
    __shared__ float sm[8][34 * 32];
    const int w    = threadIdx.x >> 5;
    const int lane = threadIdx.x & 31;
    const u32 gw   = blockIdx.x * 8 + w;       // 16384 warps
    const int b    = gw >> 10;
    const u32 base = gw << 10;

    float t1[5], t2[5];
    float C1 = load_tc<5>(thetas, b, 0, t1);
    float C2 = load_tc<5>(thetas, b, 5, t2);
    const float Ct = C1 * C2;

    u64 PX[16], PY[16];
    const float4* p4 = reinterpret_cast<const float4*>(phi + base + lane * 32);
#pragma unroll
    for (int k = 0; k < 8; ++k) {
        float4 v = __ldcs(p4 + k);
        PX[2 * k]     = pk(v.x, v.y);
        PX[2 * k + 1] = pk(v.z, v.w);
    }

    // specialized stage 0 with imag = 0: PX unchanged, PY = -t * swap(PX)
    {
        const float tn = -t1[0];
#pragma unroll
        for (int q = 0; q < 16; ++q) {
            float xl, xh; upk(PX[q], xl, xh);
            PY[q] = pk(tn * xh, tn * xl);
        }
    }
    fg_tail<16, 4>(PX, PY, t1);    // bits 1..4

    float* X = sm[w];
#pragma unroll
    for (int q = 0; q < 16; ++q) {
        float l, h; upk(PX[q], l, h);
        X[(2 * q) * 34 + lane]     = l;
        X[(2 * q + 1) * 34 + lane] = h;
    }
    __syncwarp();
#pragma unroll
    for (int q = 0; q < 16; ++q) {
        float2 v = *reinterpret_cast<float2*>(&X[lane * 34 + 2 * q]);
        PX[q] = pk(v.x, v.y);
    }
    __syncwarp();
#pragma unroll
    for (int q = 0; q < 16; ++q) {
        float l, h; upk(PY[q], l, h);
        X[(2 * q) * 34 + lane]     = l;
        X[(2 * q + 1) * 34 + lane] = h;
    }
    __syncwarp();
#pragma unroll
    for (int q = 0; q < 16; ++q) {
        float2 v = *reinterpret_cast<float2*>(&X[lane * 34 + 2 * q]);
        PY[q] = pk(v.x, v.y);
    }

    fg_stage0<16>(PX, PY, t2[0]);  // bit 5
    fg_tail<16, 4>(PX, PY, t2);    // bits 6..9

    fg_scale<16>(PX, PY, Ct);

#pragma unroll
    for (int q = 0; q < 16; ++q) {
        float xl, xh, yl, yh;
        upk(PX[q], xl, xh); upk(PY[q], yl, yh);
        __half2 h0 = __floats2half2_rn(xl, yl);
        __half2 h1 = __floats2half2_rn(xh, yh);
        g_scratch[base + (2 * q) * 32 + lane]     = *reinterpret_cast<u32*>(&h0);
        g_scratch[base + (2 * q + 1) * 32 + lane] = *reinterpret_cast<u32*>(&h1);
    }
}

// ---------------------------------------------------------------------------
// Pass B v5: global bits 10..19, low-pair packs.
// Each f32x2 pack holds two ADJACENT low elements (bit 0) which are
// spectators to all 10 stages -> every stage is pure f2fma (no stage0).
// Thread: low8 = t&7 -> low elements (2*low8, 2*low8+1); g6 = t>>3.
// Block covers 16 low x 1024 high = 16384 elements; grid 1024.
//   phase1: g6 = bits 14..19, regs q = bits 10..13     (16 LDG.64)
//   phase2: g6 = (b18..19)<<4 | (b10..13), regs = b14..17
//   phase3: g6 = (b16..17)<<4 | (b10..13), regs = (b18..19)<<2 | (b14..15)
// u64 smem slot for element group (B14_19, B10_13, low8):
//   idx = B14_19*136 + B10_13*8 + low8   (136 mod 16 = 8 -> all four access
//   patterns are verified conflict-free per 16-lane phase)
// Two barriers; transpose-2 rewrites thread-private slots. 16 STG.128 out.
// ---------------------------------------------------------------------------
#define RXB_U64_PER_ARR (64 * 136)               // 8704 u64 = 69632 B
#define RXB_SMEM_BYTES  (2 * RXB_U64_PER_ARR * 8) // 139264 B

__global__ void __launch_bounds__(512, 1)
rx_b(const float* __restrict__ thetas, float2* __restrict__ out)
{
    extern __shared__ u64 smq[];
    u64* smX = smq;
    u64* smY = smq + RXB_U64_PER_ARR;

    const int t    = threadIdx.x;
    const int low8 = t & 7;
    const int g6   = t >> 3;                   // 0..63
    const int blk   = blockIdx.x;              // 1024 blocks
    const int b     = blk >> 6;                // batch
    const int chunk = blk & 63;                // orig bits 4..9
    const u32 ub    = ((u32)b << 19) + ((u32)chunk << 3) + (u32)low8; // /2 units

    const u64* s8 = reinterpret_cast<const u64*>(g_scratch);

    float t1[4];
    float C1 = load_tc<4>(thetas, b, 10, t1);

    // ---- phase 1: regs q = bits 10..13 (g6 = bits 14..19) ----
    u64 PX[16], PY[16];
    const u32 a0 = ub + ((u32)g6 << 13);
#pragma unroll
    for (int h = 0; h < 2; ++h) {              // two batches of 8 LDG.64 (MLP)
        u64 wv[8];
#pragma unroll
        for (int k = 0; k < 8; ++k)
            wv[k] = __ldcs(&s8[a0 + ((u32)(h * 8 + k) << 9)]);
#pragma unroll
        for (int k = 0; k < 8; ++k) {
            const int q = h * 8 + k;
            u32 wlo = (u32)wv[k], whi = (u32)(wv[k] >> 32);
            float2 v0 = __half22float2(*reinterpret_cast<__half2*>(&wlo)); // elem even
            float2 v1 = __half22float2(*reinterpret_cast<__half2*>(&whi)); // elem odd
            PX[q] = pk(v0.x, v1.x);
            PY[q] = pk(v0.y, v1.y);
        }
    }

#pragma unroll
    for (int j = 0; j < 4; ++j)                // bits 10..13
        fg_mask<16>(PX, PY, t1[j], 1 << j);

    // ---- transpose 1 store: idx = g6*136 + q*8 + low8 ----
#pragma unroll
    for (int q = 0; q < 16; ++q) {
        smX[g6 * 136 + q * 8 + low8] = PX[q];
        smY[g6 * 136 + q * 8 + low8] = PY[q];
    }
    __syncthreads();

    // ---- phase 2: regs r = bits 14..17; thread h2 = b18..19, f4 = b10..13
    const int h2 = g6 >> 4;
    const int f4 = g6 & 15;
    const int rb = f4 * 8 + low8;
#pragma unroll
    for (int r = 0; r < 16; ++r) {
        PX[r] = smX[(h2 * 16 + r) * 136 + rb];
        PY[r] = smY[(h2 * 16 + r) * 136 + rb];
    }

    float t2[4];
    float C2 = load_tc<4>(thetas, b, 14, t2);
#pragma unroll
    for (int j = 0; j < 4; ++j)                // bits 14..17
        fg_mask<16>(PX, PY, t2[j], 1 << j);

    // ---- transpose 2: write back to the SAME slots (thread-private) ----
#pragma unroll
    for (int r = 0; r < 16; ++r) {
        smX[(h2 * 16 + r) * 136 + rb] = PX[r];
        smY[(h2 * 16 + r) * 136 + rb] = PY[r];
    }
    __syncthreads();

    // ---- phase 3: thread c2 = b16..17, f4 = b10..13;
    //      regs r2 = (b18..19)<<2 | (b14..15)
    const int c2 = g6 >> 4;                    // reuse decomposition
#pragma unroll
    for (int r2 = 0; r2 < 16; ++r2) {
        const int B = (r2 & 3) + c2 * 4 + (r2 >> 2) * 16;  // bits 14..19
        PX[r2] = smX[B * 136 + rb];
        PY[r2] = smY[B * 136 + rb];
    }

    float t3[2];
    float C3 = load_tc<2>(thetas, b, 18, t3);
    fg_mask<16>(PX, PY, t3[0], 4);             // bit 18
    fg_mask<16>(PX, PY, t3[1], 8);             // bit 19

    fg_scale<16>(PX, PY, C1 * C2 * C3);

    // ---- store: 16 STG.128 (two consecutive float2 per thread) ----
    float4* o4 = reinterpret_cast<float4*>(out);
    const u32 a1 = ub + ((u32)f4 << 9) + ((u32)c2 << 15);
#pragma unroll
    for (int r2 = 0; r2 < 16; ++r2) {
        float xl, xh, yl, yh;
        upk(PX[r2], xl, xh); upk(PY[r2], yl, yh);
        __stcs(&o4[a1 + ((u32)(r2 & 3) << 13) + ((u32)(r2 >> 2) << 17)],
               make_float4(xl, yl, xh, yh));
    }
}

// ---------------------------------------------------------------------------
extern "C" void kernel_launch(void* const* d_in, const int* in_sizes, int n_in,
                              void* d_out, int out_size)
{
    const float* phi    = (const float*)d_in[0];   // [16, 2^20] float32
    const float* thetas = (const float*)d_in[1];   // [16, 20]   float32
    float2* out = (float2*)d_out;                  // [16, 2^20] (re, im)

    static int smem_set = 0;
    if (!smem_set) {
        cudaFuncSetAttribute(rx_b, cudaFuncAttributeMaxDynamicSharedMemorySize,
                             RXB_SMEM_BYTES);
        smem_set = 1;
    }

    rx_a<<<2048, 256>>>(phi, thetas);
    rx_b<<<1024, 512, RXB_SMEM_BYTES>>>(thetas, out);
}

// round 13
// speedup vs baseline: 1.0790x; 1.0790x over previous
#include <cuda_runtime.h>
#include <cuda_fp16.h>

#define NQ 20
typedef unsigned long long u64;
typedef unsigned int u32;

// 64MB scratch: fp16x2 intermediate for all 16 batches (fits 126MB L2)
__device__ u32 g_scratch[16u << 20];

// ---------------- f32x2 helpers (packed 2xfp32 ops, sm_103a) ----------------
__device__ __forceinline__ u64 pk(float lo, float hi) {
    u64 r; asm("mov.b64 %0,{%1,%2};" : "=l"(r) : "f"(lo), "f"(hi)); return r;
}
__device__ __forceinline__ void upk(u64 p, float& lo, float& hi) {
    asm("mov.b64 {%0,%1},%2;" : "=f"(lo), "=f"(hi) : "l"(p));
}
__device__ __forceinline__ u64 f2mul(u64 a, u64 b) {
    u64 r; asm("mul.rn.f32x2 %0,%1,%2;" : "=l"(r) : "l"(a), "l"(b)); return r;
}
__device__ __forceinline__ u64 f2fma(u64 a, u64 b, u64 c) {
    u64 r; asm("fma.rn.f32x2 %0,%1,%2,%3;" : "=l"(r) : "l"(a), "l"(b), "l"(c)); return r;
}

// ---------------- fast-Givens RX stages ----------------
// Unscaled update with t = tan(th/2):
//   ax' = ax + t*by ; ay' = ay - t*bx ; bx' = bx + t*ay ; by' = by - t*ax
// True result = (prod of cos) * unscaled; scale applied once per phase pair.

template<int NP>
__device__ __forceinline__ void fg_stage0(u64* PX, u64* PY, float tt)
{
#pragma unroll
    for (int q = 0; q < NP; ++q) {
        float xl, xh, yl, yh;
        upk(PX[q], xl, xh); upk(PY[q], yl, yh);
        PX[q] = pk(fmaf(tt, yh, xl), fmaf(tt, yl, xh));
        PY[q] = pk(fmaf(-tt, xh, yl), fmaf(-tt, xl, yh));
    }
}

template<int NP>
__device__ __forceinline__ void fg_mask(u64* PX, u64* PY, float tv, int pm)
{
    u64 t2  = pk(tv,  tv);
    u64 tn2 = pk(-tv, -tv);
#pragma unroll
    for (int q = 0; q < NP; ++q) {
        if (!(q & pm)) {
            const int q2 = q | pm;
            u64 ax = PX[q], bx = PX[q2];
            PX[q]  = f2fma(t2,  PY[q2], ax);
            PX[q2] = f2fma(t2,  PY[q],  bx);
            PY[q]  = f2fma(tn2, bx, PY[q]);
            PY[q2] = f2fma(tn2, ax, PY[q2]);
        }
    }
}

template<int NP, int JMAX>
__device__ __forceinline__ void fg_tail(u64* PX, u64* PY, const float* t)
{
#pragma unroll
    for (int j = 1; j <= JMAX; ++j)
        fg_mask<NP>(PX, PY, t[j], 1 << (j - 1));
}

template<int NP>
__device__ __forceinline__ void fg_scale(u64* PX, u64* PY, float C)
{
    u64 C2 = pk(C, C);
#pragma unroll
    for (int q = 0; q < NP; ++q) {
        PX[q] = f2mul(C2, PX[q]);
        PY[q] = f2mul(C2, PY[q]);
    }
}

// qubit i = most-significant bit => global bit g maps to theta index (19-g)
template<int N>
__device__ __forceinline__ float load_tc(const float* __restrict__ thetas, int b,
                                         int gbase, float* t)
{
    float C = 1.0f;
#pragma unroll
    for (int j = 0; j < N; ++j) {
        float th = thetas[b * NQ + (NQ - 1 - (gbase + j))];
        float s, c;
        __sincosf(0.5f * th, &s, &c);
        t[j] = __fdividef(s, c);
        C *= c;
    }
    return C;
}

// ---------------------------------------------------------------------------
// Pass A (unchanged, R7-best): global bits 0..9, all 16 batches. Warp owns
// 1024 contiguous elements. phi streamed in (__ldcs); fp16x2 to scratch.
// ---------------------------------------------------------------------------
__global__ void __launch_bounds__(256)
rx_a(const float* __restrict__ phi, const float* __restrict__ thetas)
{
    __shared__ float sm[8][34 * 32];
    const int w    = threadIdx.x >> 5;
    const int lane = threadIdx.x & 31;
    const u32 gw   = blockIdx.x * 8 + w;       // 16384 warps
    const int b    = gw >> 10;
    const u32 base = gw << 10;

    float t1[5], t2[5];
    float C1 = load_tc<5>(thetas, b, 0, t1);
    float C2 = load_tc<5>(thetas, b, 5, t2);
    const float Ct = C1 * C2;

    u64 PX[16], PY[16];
    const float4* p4 = reinterpret_cast<const float4*>(phi + base + lane * 32);
#pragma unroll
    for (int k = 0; k < 8; ++k) {
        float4 v = __ldcs(p4 + k);
        PX[2 * k]     = pk(v.x, v.y);
        PX[2 * k + 1] = pk(v.z, v.w);
    }

    // specialized stage 0 with imag = 0: PX unchanged, PY = -t * swap(PX)
    {
        const float tn = -t1[0];
#pragma unroll
        for (int q = 0; q < 16; ++q) {
            float xl, xh; upk(PX[q], xl, xh);
            PY[q] = pk(tn * xh, tn * xl);
        }
    }
    fg_tail<16, 4>(PX, PY, t1);    // bits 1..4

    float* X = sm[w];
#pragma unroll
    for (int q = 0; q < 16; ++q) {
        float l, h; upk(PX[q], l, h);
        X[(2 * q) * 34 + lane]     = l;
        X[(2 * q + 1) * 34 + lane] = h;
    }
    __syncwarp();
#pragma unroll
    for (int q = 0; q < 16; ++q) {
        float2 v = *reinterpret_cast<float2*>(&X[lane * 34 + 2 * q]);
        PX[q] = pk(v.x, v.y);
    }
    __syncwarp();
#pragma unroll
    for (int q = 0; q < 16; ++q) {
        float l, h; upk(PY[q], l, h);
        X[(2 * q) * 34 + lane]     = l;
        X[(2 * q + 1) * 34 + lane] = h;
    }
    __syncwarp();
#pragma unroll
    for (int q = 0; q < 16; ++q) {
        float2 v = *reinterpret_cast<float2*>(&X[lane * 34 + 2 * q]);
        PY[q] = pk(v.x, v.y);
    }

    fg_stage0<16>(PX, PY, t2[0]);  // bit 5
    fg_tail<16, 4>(PX, PY, t2);    // bits 6..9

    fg_scale<16>(PX, PY, Ct);

#pragma unroll
    for (int q = 0; q < 16; ++q) {
        float xl, xh, yl, yh;
        upk(PX[q], xl, xh); upk(PY[q], yl, yh);
        __half2 h0 = __floats2half2_rn(xl, yl);
        __half2 h1 = __floats2half2_rn(xh, yh);
        g_scratch[base + (2 * q) * 32 + lane]     = *reinterpret_cast<u32*>(&h0);
        g_scratch[base + (2 * q + 1) * 32 + lane] = *reinterpret_cast<u32*>(&h1);
    }
}

// ---------------------------------------------------------------------------
// Pass B (R9 transpose + R7 cache policy): global bits 10..19, all 16
// batches. Scratch reads __ldcs (evict-first; frees L2 in the replay loop —
// measured ~10us steady-state effect R7 vs R9). Conflict-free 32-bit
// transpose into two smem buffers (X, Y) with a single __syncthreads.
// Final fp32 out with __stcs.
// Layout per buffer: float (i5, j5, low) at i5*264 + j5*8 + low
//   store: fixed j -> banks (8*g5 + low) mod 32, all 32 distinct
//   read:  fixed j -> g5*8+low = 0..31 consecutive
// ---------------------------------------------------------------------------
__global__ void __launch_bounds__(256)
rx_b(const float* __restrict__ thetas, float2* __restrict__ out)
{
    __shared__ float smX[32 * 264];            // 33792 B
    __shared__ float smY[32 * 264];            // 33792 B
    const int t   = threadIdx.x;
    const int low = t & 7;
    const int g5  = t >> 3;
    const int blk   = blockIdx.x;              // 2048 blocks
    const int b     = blk >> 7;
    const int chunk = blk & 127;
    const u32 base  = ((u32)b << 20) + ((u32)chunk << 3) + (u32)low;

    float t1[5];
    float C1 = load_tc<5>(thetas, b, 10, t1);

    // loads: two batches of 16 issued before their converts (MLP), __ldcs
    u64 PX[16], PY[16];
    const u32 a0 = base + ((u32)g5 << 15);
#pragma unroll
    for (int h = 0; h < 2; ++h) {
        u32 wv[16];
#pragma unroll
        for (int k = 0; k < 16; ++k)
            wv[k] = __ldcs(&g_scratch[a0 + (u32)(h * 16 + k) * 1024u]);
#pragma unroll
        for (int k = 0; k < 8; ++k) {
            const int q = h * 8 + k;
            float2 v0 = __half22float2(*reinterpret_cast<__half2*>(&wv[2 * k]));
            float2 v1 = __half22float2(*reinterpret_cast<__half2*>(&wv[2 * k + 1]));
            PX[q] = pk(v0.x, v1.x);
            PY[q] = pk(v0.y, v1.y);
        }
    }

    fg_stage0<16>(PX, PY, t1[0]);  // bit 10
    fg_tail<16, 4>(PX, PY, t1);    // bits 11..14

    // store X and Y into separate buffers, one barrier (conflict-free)
#pragma unroll
    for (int q = 0; q < 16; ++q) {
        float xl, xh, yl, yh;
        upk(PX[q], xl, xh); upk(PY[q], yl, yh);
        smX[g5 * 264 + (2 * q) * 8 + low]     = xl;
        smX[g5 * 264 + (2 * q + 1) * 8 + low] = xh;
        smY[g5 * 264 + (2 * q) * 8 + low]     = yl;
        smY[g5 * 264 + (2 * q + 1) * 8 + low] = yh;
    }
    __syncthreads();

#pragma unroll
    for (int q = 0; q < 16; ++q) {
        PX[q] = pk(smX[(2 * q) * 264 + g5 * 8 + low],
                   smX[(2 * q + 1) * 264 + g5 * 8 + low]);
        PY[q] = pk(smY[(2 * q) * 264 + g5 * 8 + low],
                   smY[(2 * q + 1) * 264 + g5 * 8 + low]);
    }

    float t2[5];
    float C2 = load_tc<5>(thetas, b, 15, t2);

    fg_stage0<16>(PX, PY, t2[0]);  // bit 15
    fg_tail<16, 4>(PX, PY, t2);    // bits 16..19

    fg_scale<16>(PX, PY, C1 * C2);

    const u32 a1 = base + ((u32)g5 << 10);
#pragma unroll
    for (int q = 0; q < 16; ++q) {
        float xl, xh, yl, yh;
        upk(PX[q], xl, xh); upk(PY[q], yl, yh);
        __stcs(&out[a1 + ((u32)(2 * q) << 15)],     make_float2(xl, yl));
        __stcs(&out[a1 + ((u32)(2 * q + 1) << 15)], make_float2(xh, yh));
    }
}

// ---------------------------------------------------------------------------
extern "C" void kernel_launch(void* const* d_in, const int* in_sizes, int n_in,
                              void* d_out, int out_size)
{
    const float* phi    = (const float*)d_in[0];   // [16, 2^20] float32
    const float* thetas = (const float*)d_in[1];   // [16, 20]   float32
    float2* out = (float2*)d_out;                  // [16, 2^20] (re, im)

    rx_a<<<2048, 256>>>(phi, thetas);
    rx_b<<<2048, 256>>>(thetas, out);
}

// round 14
// speedup vs baseline: 1.0884x; 1.0087x over previous
#include <cuda_runtime.h>
#include <cuda_fp16.h>

#define NQ 20
typedef unsigned long long u64;
typedef unsigned int u32;

// 64MB scratch: fp16x2 intermediate for all 16 batches (fits 126MB L2)
__device__ u32 g_scratch[16u << 20];

// ---------------- f32x2 helpers (packed 2xfp32 ops, sm_103a) ----------------
__device__ __forceinline__ u64 pk(float lo, float hi) {
    u64 r; asm("mov.b64 %0,{%1,%2};" : "=l"(r) : "f"(lo), "f"(hi)); return r;
}
__device__ __forceinline__ void upk(u64 p, float& lo, float& hi) {
    asm("mov.b64 {%0,%1},%2;" : "=f"(lo), "=f"(hi) : "l"(p));
}
__device__ __forceinline__ u64 f2mul(u64 a, u64 b) {
    u64 r; asm("mul.rn.f32x2 %0,%1,%2;" : "=l"(r) : "l"(a), "l"(b)); return r;
}
__device__ __forceinline__ u64 f2fma(u64 a, u64 b, u64 c) {
    u64 r; asm("fma.rn.f32x2 %0,%1,%2,%3;" : "=l"(r) : "l"(a), "l"(b), "l"(c)); return r;
}

// ---------------- fast-Givens RX stages ----------------
// Unscaled update with t = tan(th/2):
//   ax' = ax + t*by ; ay' = ay - t*bx ; bx' = bx + t*ay ; by' = by - t*ax
// True result = (prod of cos) * unscaled; scale applied once per phase pair.

template<int NP>
__device__ __forceinline__ void fg_stage0(u64* PX, u64* PY, float tt)
{
#pragma unroll
    for (int q = 0; q < NP; ++q) {
        float xl, xh, yl, yh;
        upk(PX[q], xl, xh); upk(PY[q], yl, yh);
        PX[q] = pk(fmaf(tt, yh, xl), fmaf(tt, yl, xh));
        PY[q] = pk(fmaf(-tt, xh, yl), fmaf(-tt, xl, yh));
    }
}

template<int NP>
__device__ __forceinline__ void fg_mask(u64* PX, u64* PY, float tv, int pm)
{
    u64 t2  = pk(tv,  tv);
    u64 tn2 = pk(-tv, -tv);
#pragma unroll
    for (int q = 0; q < NP; ++q) {
        if (!(q & pm)) {
            const int q2 = q | pm;
            u64 ax = PX[q], bx = PX[q2];
            PX[q]  = f2fma(t2,  PY[q2], ax);
            PX[q2] = f2fma(t2,  PY[q],  bx);
            PY[q]  = f2fma(tn2, bx, PY[q]);
            PY[q2] = f2fma(tn2, ax, PY[q2]);
        }
    }
}

template<int NP, int JMAX>
__device__ __forceinline__ void fg_tail(u64* PX, u64* PY, const float* t)
{
#pragma unroll
    for (int j = 1; j <= JMAX; ++j)
        fg_mask<NP>(PX, PY, t[j], 1 << (j - 1));
}

template<int NP>
__device__ __forceinline__ void fg_scale(u64* PX, u64* PY, float C)
{
    u64 C2 = pk(C, C);
#pragma unroll
    for (int q = 0; q < NP; ++q) {
        PX[q] = f2mul(C2, PX[q]);
        PY[q] = f2mul(C2, PY[q]);
    }
}

// qubit i = most-significant bit => global bit g maps to theta index (19-g)
template<int N>
__device__ __forceinline__ float load_tc(const float* __restrict__ thetas, int b,
                                         int gbase, float* t)
{
    float C = 1.0f;
#pragma unroll
    for (int j = 0; j < N; ++j) {
        float th = thetas[b * NQ + (NQ - 1 - (gbase + j))];
        float s, c;
        __sincosf(0.5f * th, &s, &c);
        t[j] = __fdividef(s, c);
        C *= c;
    }
    return C;
}

// ---------------------------------------------------------------------------
// Pass A (R7 exact, measured 18us): global bits 0..9, all 16 batches in one
// launch. Warp owns 1024 contiguous elements. phi streamed in (__ldcs);
// fp16x2 intermediate to scratch (default policy -> L2-resident for pass B).
// ---------------------------------------------------------------------------
__global__ void __launch_bounds__(256)
rx_a(const float* __restrict__ phi, const float* __restrict__ thetas)
{
    __shared__ float sm[8][34 * 32];
    const int w    = threadIdx.x >> 5;
    const int lane = threadIdx.x & 31;
    const u32 gw   = blockIdx.x * 8 + w;       // 16384 warps
    const int b    = gw >> 10;
    const u32 base = gw << 10;

    float t1[5], t2[5];
    float C1 = load_tc<5>(thetas, b, 0, t1);
    float C2 = load_tc<5>(thetas, b, 5, t2);
    const float Ct = C1 * C2;

    u64 PX[16], PY[16];
    const float4* p4 = reinterpret_cast<const float4*>(phi + base + lane * 32);
#pragma unroll
    for (int k = 0; k < 8; ++k) {
        float4 v = __ldcs(p4 + k);
        PX[2 * k]     = pk(v.x, v.y);
        PX[2 * k + 1] = pk(v.z, v.w);
    }

    // specialized stage 0 with imag = 0: PX unchanged, PY = -t * swap(PX)
    {
        const float tn = -t1[0];
#pragma unroll
        for (int q = 0; q < 16; ++q) {
            float xl, xh; upk(PX[q], xl, xh);
            PY[q] = pk(tn * xh, tn * xl);
        }
    }
    fg_tail<16, 4>(PX, PY, t1);    // bits 1..4

    float* X = sm[w];
#pragma unroll
    for (int q = 0; q < 16; ++q) {
        float l, h; upk(PX[q], l, h);
        X[(2 * q) * 34 + lane]     = l;
        X[(2 * q + 1) * 34 + lane] = h;
    }
    __syncwarp();
#pragma unroll
    for (int q = 0; q < 16; ++q) {
        float2 v = *reinterpret_cast<float2*>(&X[lane * 34 + 2 * q]);
        PX[q] = pk(v.x, v.y);
    }
    __syncwarp();
#pragma unroll
    for (int q = 0; q < 16; ++q) {
        float l, h; upk(PY[q], l, h);
        X[(2 * q) * 34 + lane]     = l;
        X[(2 * q + 1) * 34 + lane] = h;
    }
    __syncwarp();
#pragma unroll
    for (int q = 0; q < 16; ++q) {
        float2 v = *reinterpret_cast<float2*>(&X[lane * 34 + 2 * q]);
        PY[q] = pk(v.x, v.y);
    }

    fg_stage0<16>(PX, PY, t2[0]);  // bit 5
    fg_tail<16, 4>(PX, PY, t2);    // bits 6..9

    fg_scale<16>(PX, PY, Ct);

#pragma unroll
    for (int q = 0; q < 16; ++q) {
        float xl, xh, yl, yh;
        upk(PX[q], xl, xh); upk(PY[q], yl, yh);
        __half2 h0 = __floats2half2_rn(xl, yl);
        __half2 h1 = __floats2half2_rn(xh, yh);
        g_scratch[base + (2 * q) * 32 + lane]     = *reinterpret_cast<u32*>(&h0);
        g_scratch[base + (2 * q + 1) * 32 + lane] = *reinterpret_cast<u32*>(&h1);
    }
}

// ---------------------------------------------------------------------------
// Pass B (R6 exact structure, measured 22us/launch): global bits 10..19 for
// an 8-batch group. Plain scratch loads (default policy; group's 32MB half
// stays resident), 264-pad conflict-free 32-bit transpose (single buffer,
// 4 barriers), __stcs final stores (dead data -> evict-first, so B0's output
// doesn't evict B1's scratch half).
// ---------------------------------------------------------------------------
__global__ void __launch_bounds__(256)
rx_b(const float* __restrict__ thetas, float2* __restrict__ out, int batch_base)
{
    __shared__ float sm[32 * 264];
    const int t   = threadIdx.x;
    const int low = t & 7;
    const int g5  = t >> 3;
    const int blk   = blockIdx.x;              // 1024 blocks per group
    const int b     = batch_base + (blk >> 7);
    const int chunk = blk & 127;
    const u32 base  = ((u32)b << 20) + ((u32)chunk << 3) + (u32)low;

    float t1[5], t2[5];
    float C1 = load_tc<5>(thetas, b, 10, t1);
    float C2 = load_tc<5>(thetas, b, 15, t2);

    u64 PX[16], PY[16];
    const u32 a0 = base + ((u32)g5 << 15);
#pragma unroll
    for (int q = 0; q < 16; ++q) {
        u32 w0 = g_scratch[a0 + ((u32)(2 * q) << 10)];
        u32 w1 = g_scratch[a0 + ((u32)(2 * q + 1) << 10)];
        float2 v0 = __half22float2(*reinterpret_cast<__half2*>(&w0));
        float2 v1 = __half22float2(*reinterpret_cast<__half2*>(&w1));
        PX[q] = pk(v0.x, v1.x);
        PY[q] = pk(v0.y, v1.y);
    }

    fg_stage0<16>(PX, PY, t1[0]);  // bit 10
    fg_tail<16, 4>(PX, PY, t1);    // bits 11..14

    // transpose X then Y through one buffer (conflict-free 264 pad)
#pragma unroll
    for (int q = 0; q < 16; ++q) {
        float l, h; upk(PX[q], l, h);
        sm[g5 * 264 + (2 * q) * 8 + low]     = l;
        sm[g5 * 264 + (2 * q + 1) * 8 + low] = h;
    }
    __syncthreads();
#pragma unroll
    for (int q = 0; q < 16; ++q) {
        float l = sm[(2 * q) * 264 + g5 * 8 + low];
        float h = sm[(2 * q + 1) * 264 + g5 * 8 + low];
        PX[q] = pk(l, h);
    }
    __syncthreads();
#pragma unroll
    for (int q = 0; q < 16; ++q) {
        float l, h; upk(PY[q], l, h);
        sm[g5 * 264 + (2 * q) * 8 + low]     = l;
        sm[g5 * 264 + (2 * q + 1) * 8 + low] = h;
    }
    __syncthreads();
#pragma unroll
    for (int q = 0; q < 16; ++q) {
        float l = sm[(2 * q) * 264 + g5 * 8 + low];
        float h = sm[(2 * q + 1) * 264 + g5 * 8 + low];
        PY[q] = pk(l, h);
    }

    fg_stage0<16>(PX, PY, t2[0]);  // bit 15
    fg_tail<16, 4>(PX, PY, t2);    // bits 16..19

    fg_scale<16>(PX, PY, C1 * C2);

    const u32 a1 = base + ((u32)g5 << 10);
#pragma unroll
    for (int q = 0; q < 16; ++q) {
        float xl, xh, yl, yh;
        upk(PX[q], xl, xh); upk(PY[q], yl, yh);
        __stcs(&out[a1 + ((u32)(2 * q) << 15)],     make_float2(xl, yl));
        __stcs(&out[a1 + ((u32)(2 * q + 1) << 15)], make_float2(xh, yh));
    }
}

// ---------------------------------------------------------------------------
extern "C" void kernel_launch(void* const* d_in, const int* in_sizes, int n_in,
                              void* d_out, int out_size)
{
    const float* phi    = (const float*)d_in[0];   // [16, 2^20] float32
    const float* thetas = (const float*)d_in[1];   // [16, 20]   float32
    float2* out = (float2*)d_out;                  // [16, 2^20] (re, im)

    // Single full-width pass A (R7-measured 18us), then pass B in two
    // 8-batch groups (R6-measured 22us each: 32MB working set per group).
    rx_a<<<2048, 256>>>(phi, thetas);
    rx_b<<<1024, 256>>>(thetas, out, 0);
    rx_b<<<1024, 256>>>(thetas, out, 8);
}

// round 15
// speedup vs baseline: 1.1418x; 1.0491x over previous
#include <cuda_runtime.h>
#include <cuda_fp16.h>

#define NQ 20
typedef unsigned long long u64;
typedef unsigned int u32;

// 64MB scratch: fp16x2 intermediate for all 16 batches (fits 126MB L2)
__device__ u32 g_scratch[16u << 20];

// ---------------- f32x2 helpers (packed 2xfp32 ops, sm_103a) ----------------
__device__ __forceinline__ u64 pk(float lo, float hi) {
    u64 r; asm("mov.b64 %0,{%1,%2};" : "=l"(r) : "f"(lo), "f"(hi)); return r;
}
__device__ __forceinline__ void upk(u64 p, float& lo, float& hi) {
    asm("mov.b64 {%0,%1},%2;" : "=f"(lo), "=f"(hi) : "l"(p));
}
__device__ __forceinline__ u64 f2mul(u64 a, u64 b) {
    u64 r; asm("mul.rn.f32x2 %0,%1,%2;" : "=l"(r) : "l"(a), "l"(b)); return r;
}
__device__ __forceinline__ u64 f2fma(u64 a, u64 b, u64 c) {
    u64 r; asm("fma.rn.f32x2 %0,%1,%2,%3;" : "=l"(r) : "l"(a), "l"(b), "l"(c)); return r;
}

// ---------------- fast-Givens RX stages ----------------
// Unscaled update with t = tan(th/2):
//   ax' = ax + t*by ; ay' = ay - t*bx ; bx' = bx + t*ay ; by' = by - t*ax
// True result = (prod of cos) * unscaled; scale applied once per phase pair.

// stage 0: element mask 1 (intra-pack), scalar fma on the halves
__device__ __forceinline__ void stage0_fg(u64 PX[16], u64 PY[16], float tt)
{
#pragma unroll
    for (int q = 0; q < 16; ++q) {
        float xl, xh, yl, yh;
        upk(PX[q], xl, xh); upk(PY[q], yl, yh);
        PX[q] = pk(fmaf(tt, yh, xl), fmaf(tt, yl, xh));
        PY[q] = pk(fmaf(-tt, xh, yl), fmaf(-tt, xl, yh));
    }
}

// stages 1..4: pack-level pairs, 4 f2fma per pair
__device__ __forceinline__ void stages_fg_tail(u64 PX[16], u64 PY[16], const float t[5])
{
#pragma unroll
    for (int j = 1; j < 5; ++j) {
        u64 t2  = pk(t[j],  t[j]);
        u64 tn2 = pk(-t[j], -t[j]);
        const int pm = 1 << (j - 1);
#pragma unroll
        for (int q = 0; q < 16; ++q) {
            if (!(q & pm)) {
                const int q2 = q | pm;
                u64 ax = PX[q], bx = PX[q2];
                PX[q]  = f2fma(t2,  PY[q2], ax);
                PX[q2] = f2fma(t2,  PY[q],  bx);
                PY[q]  = f2fma(tn2, bx, PY[q]);
                PY[q2] = f2fma(tn2, ax, PY[q2]);
            }
        }
    }
}

__device__ __forceinline__ void scale_all(u64 PX[16], u64 PY[16], float C)
{
    u64 C2 = pk(C, C);
#pragma unroll
    for (int q = 0; q < 16; ++q) {
        PX[q] = f2mul(C2, PX[q]);
        PY[q] = f2mul(C2, PY[q]);
    }
}

// qubit i = most-significant bit => global bit g maps to theta index (19-g)
// fills t[j] = tan(th/2), returns product of cos(th/2)
__device__ __forceinline__ float load_tc(const float* __restrict__ thetas, int b,
                                         int gbit_base, float t[5])
{
    float C = 1.0f;
#pragma unroll
    for (int j = 0; j < 5; ++j) {
        float th = thetas[b * NQ + (NQ - 1 - (gbit_base + j))];
        float s, c;
        __sincosf(0.5f * th, &s, &c);
        t[j] = __fdividef(s, c);
        C *= c;
    }
    return C;
}

// ---------------------------------------------------------------------------
// Pass A: global bits 0..9, all 16 batches. Warp owns 1024 contiguous
// elements. phi streamed in (__ldcs); fp16x2 intermediate to scratch
// (default policy: stays L2-resident for pass B).
// ---------------------------------------------------------------------------
__global__ void __launch_bounds__(256)
rx_a(const float* __restrict__ phi, const float* __restrict__ thetas)
{
    __shared__ float sm[8][34 * 32];
    const int w    = threadIdx.x >> 5;
    const int lane = threadIdx.x & 31;
    const u32 gw   = blockIdx.x * 8 + w;       // 16384 warps
    const int b    = gw >> 10;
    const u32 base = gw << 10;

    float t1[5], t2[5];
    float C1 = load_tc(thetas, b, 0, t1);
    float C2 = load_tc(thetas, b, 5, t2);
    const float Ct = C1 * C2;

    u64 PX[16], PY[16];
    const float4* p4 = reinterpret_cast<const float4*>(phi + base + lane * 32);
#pragma unroll
    for (int k = 0; k < 8; ++k) {
        float4 v = __ldcs(p4 + k);
        PX[2 * k]     = pk(v.x, v.y);
        PX[2 * k + 1] = pk(v.z, v.w);
    }

    // specialized stage 0 with imag = 0: PX unchanged, PY = -t * swap(PX)
    {
        const float tn = -t1[0];
#pragma unroll
        for (int q = 0; q < 16; ++q) {
            float xl, xh; upk(PX[q], xl, xh);
            PY[q] = pk(tn * xh, tn * xl);
        }
    }
    stages_fg_tail(PX, PY, t1);    // bits 1..4

    float* X = sm[w];
#pragma unroll
    for (int q = 0; q < 16; ++q) {
        float l, h; upk(PX[q], l, h);
        X[(2 * q) * 34 + lane]     = l;
        X[(2 * q + 1) * 34 + lane] = h;
    }
    __syncwarp();
#pragma unroll
    for (int q = 0; q < 16; ++q) {
        float2 v = *reinterpret_cast<float2*>(&X[lane * 34 + 2 * q]);
        PX[q] = pk(v.x, v.y);
    }
    __syncwarp();
#pragma unroll
    for (int q = 0; q < 16; ++q) {
        float l, h; upk(PY[q], l, h);
        X[(2 * q) * 34 + lane]     = l;
        X[(2 * q + 1) * 34 + lane] = h;
    }
    __syncwarp();
#pragma unroll
    for (int q = 0; q < 16; ++q) {
        float2 v = *reinterpret_cast<float2*>(&X[lane * 34 + 2 * q]);
        PY[q] = pk(v.x, v.y);
    }

    stage0_fg(PX, PY, t2[0]);      // bit 5
    stages_fg_tail(PX, PY, t2);    // bits 6..9

    scale_all(PX, PY, Ct);         // apply deferred cos product once

#pragma unroll
    for (int q = 0; q < 16; ++q) {
        float xl, xh, yl, yh;
        upk(PX[q], xl, xh); upk(PY[q], yl, yh);
        __half2 h0 = __floats2half2_rn(xl, yl);
        __half2 h1 = __floats2half2_rn(xh, yh);
        g_scratch[base + (2 * q) * 32 + lane]     = *reinterpret_cast<u32*>(&h0);
        g_scratch[base + (2 * q + 1) * 32 + lane] = *reinterpret_cast<u32*>(&h1);
    }
}

// ---------------------------------------------------------------------------
// Pass B: global bits 10..19, all 16 batches.
// Reads fp16x2 intermediate with __ldcs (evict-first: frees L2 capacity in
// the replay steady state), writes final fp32 out (__stcs).
// Single-barrier transpose: X and Y pack-stored (STS64) into two smem
// regions, one __syncthreads, then 32-bit gathers.
// Pack-store layout per array: u64 at [i5]*136 + [j5pair]*8 + [low]
//   -> float (i5, j5) at i5*272 + (j5>>1)*16 + low*2 + (j5&1)
// ---------------------------------------------------------------------------
__global__ void __launch_bounds__(256)
rx_b(const float* __restrict__ thetas, float2* __restrict__ out)
{
    __shared__ u64 smq[2 * 32 * 136];          // 69632 B
    const int t   = threadIdx.x;
    const int low = t & 7;
    const int g5  = t >> 3;
    const int blk   = blockIdx.x;              // 2048 blocks
    const int b     = blk >> 7;
    const int chunk = blk & 127;
    const u32 base  = ((u32)b << 20) + ((u32)chunk << 3) + (u32)low;

    float t1[5];
    float C1 = load_tc(thetas, b, 10, t1);

    // loads: two batches of 16 issued before their converts (MLP)
    u64 PX[16], PY[16];
    const u32 a0 = base + ((u32)g5 << 15);
#pragma unroll
    for (int h = 0; h < 2; ++h) {
        u32 wv[16];
#pragma unroll
        for (int k = 0; k < 16; ++k)
            wv[k] = __ldcs(&g_scratch[a0 + (u32)(h * 16 + k) * 1024u]);
#pragma unroll
        for (int k = 0; k < 8; ++k) {
            const int q = h * 8 + k;
            float2 v0 = __half22float2(*reinterpret_cast<__half2*>(&wv[2 * k]));
            float2 v1 = __half22float2(*reinterpret_cast<__half2*>(&wv[2 * k + 1]));
            PX[q] = pk(v0.x, v1.x);
            PY[q] = pk(v0.y, v1.y);
        }
    }

    stage0_fg(PX, PY, t1[0]);      // bit 10
    stages_fg_tail(PX, PY, t1);    // bits 11..14

    // pack-store X and Y (STS64), one barrier
#pragma unroll
    for (int q = 0; q < 16; ++q) {
        smq[g5 * 136 + q * 8 + low]              = PX[q];
        smq[32 * 136 + g5 * 136 + q * 8 + low]   = PY[q];
    }
    __syncthreads();

    const float* smf = reinterpret_cast<const float*>(smq);
    const int ro = ((g5 >> 1) << 4) + (low << 1) + (g5 & 1);
#pragma unroll
    for (int q = 0; q < 16; ++q) {
        PX[q] = pk(smf[(2 * q) * 272 + ro],        smf[(2 * q + 1) * 272 + ro]);
        PY[q] = pk(smf[8704 + (2 * q) * 272 + ro], smf[8704 + (2 * q + 1) * 272 + ro]);
    }

    float t2[5];
    float C2 = load_tc(thetas, b, 15, t2);

    stage0_fg(PX, PY, t2[0]);      // bit 15
    stages_fg_tail(PX, PY, t2);    // bits 16..19

    scale_all(PX, PY, C1 * C2);

    const u32 a1 = base + ((u32)g5 << 10);
#pragma unroll
    for (int q = 0; q < 16; ++q) {
        float xl, xh, yl, yh;
        upk(PX[q], xl, xh); upk(PY[q], yl, yh);
        __stcs(&out[a1 + ((u32)(2 * q) << 15)],     make_float2(xl, yl));
        __stcs(&out[a1 + ((u32)(2 * q + 1) << 15)], make_float2(xh, yh));
    }
}

// ---------------------------------------------------------------------------
extern "C" void kernel_launch(void* const* d_in, const int* in_sizes, int n_in,
                              void* d_out, int out_size)
{
    const float* phi    = (const float*)d_in[0];   // [16, 2^20] float32
    const float* thetas = (const float*)d_in[1];   // [16, 20]   float32
    float2* out = (float2*)d_out;                  // [16, 2^20] (re, im)

    rx_a<<<2048, 256>>>(phi, thetas);
    rx_b<<<2048, 256>>>(thetas, out);
}